// round 2
// baseline (speedup 1.0000x reference)
#include <cuda_runtime.h>
#include <math.h>

#define EMBED 1024
#define HEADS 16
#define HDIM  64
#define BATCH 4
#define SEQ   2048
#define MTOT  (BATCH * SEQ)   /* 8192 */

// ---- scratch (device globals; no allocations allowed) ----
__device__ float g_Q[BATCH * HEADS * SEQ * HDIM];  // [B][H][N][Dh]
__device__ float g_K[BATCH * HEADS * SEQ * HDIM];
__device__ float g_V[BATCH * HEADS * SEQ * HDIM];
__device__ float g_C[MTOT * EMBED];                // attention ctx, [B][N][D]

// ============================================================================
// NT SGEMM: C[m][n] = sum_k A[m][k] * B[n][k] (+ bias[n])
// BM=BN=128, BK=8, 256 threads, 8x8 per thread.
// DST = 0/1/2 : write Q/K/V (head-split scatter [B][H][N][Dh], with bias)
// DST = 3     : plain row-major write to the `out` parameter (no bias)
// All scratch access is by-name on __device__ globals; kernel_launch issues
// only plain kernel launches (fully graph-capturable, no runtime API calls).
// ============================================================================
template <int DST>
__global__ void __launch_bounds__(256)
sgemm_nt(const float* __restrict__ A, const float* __restrict__ B,
         const float* __restrict__ bias, float* __restrict__ out)
{
    const int K = EMBED;
    __shared__ float As[8][128];
    __shared__ float Bs[8][128];

    const int tid = threadIdx.x;
    const int bm  = blockIdx.x * 128;
    const int bn  = blockIdx.y * 128;
    const int lr  = tid >> 1;          // 0..127 (load row)
    const int lc  = (tid & 1) << 2;    // 0 or 4 (load col, float4)
    const int tr  = tid >> 4;          // 0..15
    const int tc  = tid & 15;          // 0..15

    const float* Ap = A + (bm + lr) * K + lc;
    const float* Bp = B + (bn + lr) * K + lc;

    float acc[8][8];
#pragma unroll
    for (int i = 0; i < 8; i++)
#pragma unroll
        for (int j = 0; j < 8; j++) acc[i][j] = 0.f;

    for (int k0 = 0; k0 < K; k0 += 8) {
        float4 a = *(const float4*)(Ap + k0);
        float4 b = *(const float4*)(Bp + k0);
        As[lc + 0][lr] = a.x; As[lc + 1][lr] = a.y;
        As[lc + 2][lr] = a.z; As[lc + 3][lr] = a.w;
        Bs[lc + 0][lr] = b.x; Bs[lc + 1][lr] = b.y;
        Bs[lc + 2][lr] = b.z; Bs[lc + 3][lr] = b.w;
        __syncthreads();

#pragma unroll
        for (int kk = 0; kk < 8; kk++) {
            float ra[8], rb[8];
            *(float4*)(ra)     = *(const float4*)&As[kk][tr * 8];
            *(float4*)(ra + 4) = *(const float4*)&As[kk][tr * 8 + 4];
            *(float4*)(rb)     = *(const float4*)&Bs[kk][tc * 8];
            *(float4*)(rb + 4) = *(const float4*)&Bs[kk][tc * 8 + 4];
#pragma unroll
            for (int i = 0; i < 8; i++)
#pragma unroll
                for (int j = 0; j < 8; j++)
                    acc[i][j] += ra[i] * rb[j];
        }
        __syncthreads();
    }

    if (DST <= 2) {
        float* C = (DST == 0) ? g_Q : (DST == 1) ? g_K : g_V;
#pragma unroll
        for (int i = 0; i < 8; i++) {
            int row = bm + tr * 8 + i;
            int b   = row >> 11;      // / SEQ
            int tok = row & 2047;     // % SEQ
#pragma unroll
            for (int j0 = 0; j0 < 8; j0 += 4) {
                int col = bn + tc * 8 + j0;
                int h   = col >> 6;
                int dh  = col & 63;
                float4 o;
                o.x = acc[i][j0 + 0] + bias[col + 0];
                o.y = acc[i][j0 + 1] + bias[col + 1];
                o.z = acc[i][j0 + 2] + bias[col + 2];
                o.w = acc[i][j0 + 3] + bias[col + 3];
                *(float4*)&C[(((b << 4) + h) * SEQ + tok) * HDIM + dh] = o;
            }
        }
    } else {
#pragma unroll
        for (int i = 0; i < 8; i++) {
            int row = bm + tr * 8 + i;
#pragma unroll
            for (int j0 = 0; j0 < 8; j0 += 4) {
                int col = bn + tc * 8 + j0;
                float4 o;
                o.x = acc[i][j0 + 0];
                o.y = acc[i][j0 + 1];
                o.z = acc[i][j0 + 2];
                o.w = acc[i][j0 + 3];
                *(float4*)&out[row * EMBED + col] = o;
            }
        }
    }
}

// ============================================================================
// Flash attention, fp32, reads g_Q/g_K/g_V, writes g_C.
// One block = one (b, h, 64-query tile).
// 256 threads: tq = tid/16 -> 4 query rows (qi0 = 4*tq),
//              tk = tid%16 -> 4 key cols  (kj = tk + 16*j) / 4 out dims (dv0=4*tk).
// smem: Qt [d][qi] (64x64), KP = Kt [d][kj] reused as swizzled Pt [kj][qi],
//       Vs [kj][d]. 3 * 16 KB = 48 KB static.
// ============================================================================
__global__ void __launch_bounds__(256)
attn_kernel()
{
    __shared__ float Qt[64 * 64];
    __shared__ float KP[64 * 64];
    __shared__ float Vs[64 * 64];

    const int tid = threadIdx.x;
    const int tq  = tid >> 4;
    const int tk  = tid & 15;
    const int qt  = blockIdx.x;
    const int h   = blockIdx.y;
    const int b   = blockIdx.z;
    const int q0  = qt * 64;

    const float* Qb = g_Q + ((b * HEADS + h) * SEQ + q0) * HDIM;
    const float* Kb = g_K + ((b * HEADS + h) * SEQ) * HDIM;
    const float* Vb = g_V + ((b * HEADS + h) * SEQ) * HDIM;

    // Load Q tile transposed, pre-scaled by Dh^-0.5 = 0.125
#pragma unroll
    for (int r = 0; r < 4; r++) {
        int idx = tid + r * 256;
        int row = idx >> 4;
        int c4  = (idx & 15) << 2;
        float4 qv = *(const float4*)&Qb[row * HDIM + c4];
        Qt[(c4 + 0) * 64 + row] = qv.x * 0.125f;
        Qt[(c4 + 1) * 64 + row] = qv.y * 0.125f;
        Qt[(c4 + 2) * 64 + row] = qv.z * 0.125f;
        Qt[(c4 + 3) * 64 + row] = qv.w * 0.125f;
    }

    float m[4], l[4], acc[4][4];
#pragma unroll
    for (int i = 0; i < 4; i++) {
        m[i] = -INFINITY;
        l[i] = 0.f;
#pragma unroll
        for (int j = 0; j < 4; j++) acc[i][j] = 0.f;
    }
    const int qi0 = tq * 4;
    const int dv0 = tk * 4;

    for (int kv0 = 0; kv0 < SEQ; kv0 += 64) {
        __syncthreads();   // prior-iter KP/Vs reads done; Qt visible on iter 0
        // Load K transposed (Kt[d][kj]) and V direct (Vs[kj][d])
#pragma unroll
        for (int r = 0; r < 4; r++) {
            int idx = tid + r * 256;
            int row = idx >> 4;
            int c4  = (idx & 15) << 2;
            float4 kv = *(const float4*)&Kb[(kv0 + row) * HDIM + c4];
            KP[(c4 + 0) * 64 + row] = kv.x;
            KP[(c4 + 1) * 64 + row] = kv.y;
            KP[(c4 + 2) * 64 + row] = kv.z;
            KP[(c4 + 3) * 64 + row] = kv.w;
            *(float4*)&Vs[row * 64 + c4] =
                *(const float4*)&Vb[(kv0 + row) * HDIM + c4];
        }
        __syncthreads();

        // Scores: s[i][j] = sum_d Qt[d][qi0+i] * Kt[d][tk+16j]
        float s[4][4];
#pragma unroll
        for (int i = 0; i < 4; i++)
#pragma unroll
            for (int j = 0; j < 4; j++) s[i][j] = 0.f;

#pragma unroll 8
        for (int d = 0; d < 64; d++) {
            float4 qv = *(const float4*)&Qt[d * 64 + qi0];
            float k0 = KP[d * 64 + tk];
            float k1 = KP[d * 64 + tk + 16];
            float k2 = KP[d * 64 + tk + 32];
            float k3 = KP[d * 64 + tk + 48];
            s[0][0] += qv.x * k0; s[0][1] += qv.x * k1; s[0][2] += qv.x * k2; s[0][3] += qv.x * k3;
            s[1][0] += qv.y * k0; s[1][1] += qv.y * k1; s[1][2] += qv.y * k2; s[1][3] += qv.y * k3;
            s[2][0] += qv.z * k0; s[2][1] += qv.z * k1; s[2][2] += qv.z * k2; s[2][3] += qv.z * k3;
            s[3][0] += qv.w * k0; s[3][1] += qv.w * k1; s[3][2] += qv.w * k2; s[3][3] += qv.w * k3;
        }
        __syncthreads();   // everyone done reading Kt before Pt overwrites KP

        // Online softmax + write P into KP as swizzled Pt[kj][qi]
#pragma unroll
        for (int i = 0; i < 4; i++) {
            float mx = fmaxf(fmaxf(s[i][0], s[i][1]), fmaxf(s[i][2], s[i][3]));
#pragma unroll
            for (int msk = 1; msk < 16; msk <<= 1)
                mx = fmaxf(mx, __shfl_xor_sync(0xffffffffu, mx, msk));
            float mnew = fmaxf(m[i], mx);
            float rs   = __expf(m[i] - mnew);
            m[i] = mnew;
            float p0 = __expf(s[i][0] - mnew);
            float p1 = __expf(s[i][1] - mnew);
            float p2 = __expf(s[i][2] - mnew);
            float p3 = __expf(s[i][3] - mnew);
            float ps = p0 + p1 + p2 + p3;
#pragma unroll
            for (int msk = 1; msk < 16; msk <<= 1)
                ps += __shfl_xor_sync(0xffffffffu, ps, msk);
            l[i] = l[i] * rs + ps;
#pragma unroll
            for (int j = 0; j < 4; j++) acc[i][j] *= rs;

            int kj;
            kj = tk;      KP[kj * 64 + ((tq ^ (kj & 7)) << 2) + i] = p0;
            kj = tk + 16; KP[kj * 64 + ((tq ^ (kj & 7)) << 2) + i] = p1;
            kj = tk + 32; KP[kj * 64 + ((tq ^ (kj & 7)) << 2) + i] = p2;
            kj = tk + 48; KP[kj * 64 + ((tq ^ (kj & 7)) << 2) + i] = p3;
        }
        __syncthreads();

        // PV: acc[i][j] += Pt[kj][qi0+i] * Vs[kj][dv0+j]
#pragma unroll 8
        for (int kj = 0; kj < 64; kj++) {
            float4 vv = *(const float4*)&Vs[kj * 64 + dv0];
            float4 pv = *(const float4*)&KP[kj * 64 + ((tq ^ (kj & 7)) << 2)];
            acc[0][0] += pv.x * vv.x; acc[0][1] += pv.x * vv.y;
            acc[0][2] += pv.x * vv.z; acc[0][3] += pv.x * vv.w;
            acc[1][0] += pv.y * vv.x; acc[1][1] += pv.y * vv.y;
            acc[1][2] += pv.y * vv.z; acc[1][3] += pv.y * vv.w;
            acc[2][0] += pv.z * vv.x; acc[2][1] += pv.z * vv.y;
            acc[2][2] += pv.z * vv.z; acc[2][3] += pv.z * vv.w;
            acc[3][0] += pv.w * vv.x; acc[3][1] += pv.w * vv.y;
            acc[3][2] += pv.w * vv.z; acc[3][3] += pv.w * vv.w;
        }
    }

    // Epilogue: ctx[b][tok][h*64 + dv]
    float* Ob = g_C + (b * SEQ + q0) * EMBED + h * HDIM;
#pragma unroll
    for (int i = 0; i < 4; i++) {
        float inv = 1.f / l[i];
        float4 o;
        o.x = acc[i][0] * inv; o.y = acc[i][1] * inv;
        o.z = acc[i][2] * inv; o.w = acc[i][3] * inv;
        *(float4*)&Ob[(qi0 + i) * EMBED + dv0] = o;
    }
}

// Final projection reads g_C by name (A param is ignored for DST==3's input
// side; we pass g_C via a trampoline kernel argument-free read instead).
__global__ void __launch_bounds__(256)
sgemm_out(const float* __restrict__ B, float* __restrict__ out)
{
    const int K = EMBED;
    __shared__ float As[8][128];
    __shared__ float Bs[8][128];

    const int tid = threadIdx.x;
    const int bm  = blockIdx.x * 128;
    const int bn  = blockIdx.y * 128;
    const int lr  = tid >> 1;
    const int lc  = (tid & 1) << 2;
    const int tr  = tid >> 4;
    const int tc  = tid & 15;

    const float* Ap = g_C + (bm + lr) * K + lc;
    const float* Bp = B + (bn + lr) * K + lc;

    float acc[8][8];
#pragma unroll
    for (int i = 0; i < 8; i++)
#pragma unroll
        for (int j = 0; j < 8; j++) acc[i][j] = 0.f;

    for (int k0 = 0; k0 < K; k0 += 8) {
        float4 a = *(const float4*)(Ap + k0);
        float4 b = *(const float4*)(Bp + k0);
        As[lc + 0][lr] = a.x; As[lc + 1][lr] = a.y;
        As[lc + 2][lr] = a.z; As[lc + 3][lr] = a.w;
        Bs[lc + 0][lr] = b.x; Bs[lc + 1][lr] = b.y;
        Bs[lc + 2][lr] = b.z; Bs[lc + 3][lr] = b.w;
        __syncthreads();

#pragma unroll
        for (int kk = 0; kk < 8; kk++) {
            float ra[8], rb[8];
            *(float4*)(ra)     = *(const float4*)&As[kk][tr * 8];
            *(float4*)(ra + 4) = *(const float4*)&As[kk][tr * 8 + 4];
            *(float4*)(rb)     = *(const float4*)&Bs[kk][tc * 8];
            *(float4*)(rb + 4) = *(const float4*)&Bs[kk][tc * 8 + 4];
#pragma unroll
            for (int i = 0; i < 8; i++)
#pragma unroll
                for (int j = 0; j < 8; j++)
                    acc[i][j] += ra[i] * rb[j];
        }
        __syncthreads();
    }

#pragma unroll
    for (int i = 0; i < 8; i++) {
        int row = bm + tr * 8 + i;
#pragma unroll
        for (int j0 = 0; j0 < 8; j0 += 4) {
            int col = bn + tc * 8 + j0;
            float4 o;
            o.x = acc[i][j0 + 0];
            o.y = acc[i][j0 + 1];
            o.z = acc[i][j0 + 2];
            o.w = acc[i][j0 + 3];
            *(float4*)&out[row * EMBED + col] = o;
        }
    }
}

// ============================================================================
extern "C" void kernel_launch(void* const* d_in, const int* in_sizes, int n_in,
                              void* d_out, int out_size)
{
    (void)in_sizes; (void)n_in; (void)out_size;
    const float* x  = (const float*)d_in[0];
    const float* Wq = (const float*)d_in[1];
    const float* bq = (const float*)d_in[2];
    const float* Wk = (const float*)d_in[3];
    const float* bk = (const float*)d_in[4];
    const float* Wv = (const float*)d_in[5];
    const float* bv = (const float*)d_in[6];
    const float* Wo = (const float*)d_in[7];
    float* out = (float*)d_out;

    dim3 gp(MTOT / 128, EMBED / 128);   // 64 x 8
    sgemm_nt<0><<<gp, 256>>>(x, Wq, bq, nullptr);
    sgemm_nt<1><<<gp, 256>>>(x, Wk, bk, nullptr);
    sgemm_nt<2><<<gp, 256>>>(x, Wv, bv, nullptr);

    attn_kernel<<<dim3(SEQ / 64, HEADS, BATCH), 256>>>();

    sgemm_out<<<gp, 256>>>(Wo, out);
}

// round 4
// speedup vs baseline: 1.4490x; 1.4490x over previous
#include <cuda_runtime.h>
#include <math.h>
#include <stdint.h>

#define EMBED 1024
#define HEADS 16
#define HDIM  64
#define BATCH 4
#define SEQ   2048
#define MTOT  (BATCH * SEQ)   /* 8192 */

#define BK      16            /* K elements per chunk */
#define NCHUNK  (EMBED / BK)  /* 64 */
#define SSTR    20            /* smem row stride (floats): conflict-free + 16B-aligned */

// ---- scratch (device globals; no allocations allowed) ----
__device__ float g_Q[BATCH * HEADS * SEQ * HDIM];  // [B][H][N][Dh]
__device__ float g_K[BATCH * HEADS * SEQ * HDIM];
__device__ float g_V[BATCH * HEADS * SEQ * HDIM];
__device__ float g_C[MTOT * EMBED];                // attention ctx, [B][N][D]

// fp32 -> tf32 round-to-nearest (avoids biased truncation)
__device__ __forceinline__ float ftf32(float x) {
    uint32_t u;
    asm("cvt.rna.tf32.f32 %0, %1;" : "=r"(u) : "f"(x));
    return __uint_as_float(u);
}

// D += A(16x8) * B(8x8), tf32 inputs, fp32 accum
__device__ __forceinline__ void mma_tf32(float* d, const uint32_t* a, const uint32_t* b) {
    asm volatile(
        "mma.sync.aligned.m16n8k8.row.col.f32.tf32.tf32.f32 "
        "{%0,%1,%2,%3}, {%4,%5,%6,%7}, {%8,%9}, {%0,%1,%2,%3};"
        : "+f"(d[0]), "+f"(d[1]), "+f"(d[2]), "+f"(d[3])
        : "r"(a[0]), "r"(a[1]), "r"(a[2]), "r"(a[3]),
          "r"(b[0]), "r"(b[1]));
}

// ============================================================================
// mma.sync tf32 NT GEMM: C[m][n] = sum_k A[m][k] * B[n][k]  (+ bias[n])
// BM=BN=128, BK=16, 256 threads (8 warps, 2m x 4n), warp tile 64x32.
// DST = 0/1/2 : C -> g_Q/g_K/g_V head-split scatter [B][H][N][Dh], with bias.
// DST = 3     : A = g_C (by name), C -> `out` row-major, no bias.
// ============================================================================
template <int DST>
__global__ void __launch_bounds__(256, 2)
mma_gemm(const float* __restrict__ Ain, const float* __restrict__ Bw,
         const float* __restrict__ bias, float* __restrict__ out)
{
    __shared__ float sA[128 * SSTR];
    __shared__ float sB[128 * SSTR];

    const float* Asrc = (DST == 3) ? (const float*)g_C : Ain;

    const int tid = threadIdx.x;
    const int wid = tid >> 5;
    const int lane = tid & 31;
    const int lr4 = lane >> 2;          // 0..7
    const int lc4 = lane & 3;           // 0..3
    const int warp_m = (wid & 1) * 64;
    const int warp_n = (wid >> 1) * 32;
    const int bm = blockIdx.x * 128;
    const int bn = blockIdx.y * 128;

    // gmem load mapping: 2 float4 per thread per tile per chunk
    const int grow0 = tid >> 2;               // 0..63   (idx r=0)
    const int grow1 = (tid + 256) >> 2;       // 64..127 (idx r=1)
    const int gc4   = (tid & 3) << 2;         // 0,4,8,12

    float acc[4][4][4];
#pragma unroll
    for (int i = 0; i < 4; i++)
#pragma unroll
        for (int j = 0; j < 4; j++)
#pragma unroll
            for (int r = 0; r < 4; r++) acc[i][j][r] = 0.f;

    float4 pfA0, pfA1, pfB0, pfB1;
    pfA0 = *(const float4*)(Asrc + (bm + grow0) * EMBED + gc4);
    pfA1 = *(const float4*)(Asrc + (bm + grow1) * EMBED + gc4);
    pfB0 = *(const float4*)(Bw   + (bn + grow0) * EMBED + gc4);
    pfB1 = *(const float4*)(Bw   + (bn + grow1) * EMBED + gc4);

    for (int c = 0; c < NCHUNK; c++) {
        __syncthreads();   // previous chunk's fragment reads complete
        float4 t;
        t.x = ftf32(pfA0.x); t.y = ftf32(pfA0.y); t.z = ftf32(pfA0.z); t.w = ftf32(pfA0.w);
        *(float4*)&sA[grow0 * SSTR + gc4] = t;
        t.x = ftf32(pfA1.x); t.y = ftf32(pfA1.y); t.z = ftf32(pfA1.z); t.w = ftf32(pfA1.w);
        *(float4*)&sA[grow1 * SSTR + gc4] = t;
        t.x = ftf32(pfB0.x); t.y = ftf32(pfB0.y); t.z = ftf32(pfB0.z); t.w = ftf32(pfB0.w);
        *(float4*)&sB[grow0 * SSTR + gc4] = t;
        t.x = ftf32(pfB1.x); t.y = ftf32(pfB1.y); t.z = ftf32(pfB1.z); t.w = ftf32(pfB1.w);
        *(float4*)&sB[grow1 * SSTR + gc4] = t;
        __syncthreads();

        if (c + 1 < NCHUNK) {   // prefetch next chunk (overlaps with mma below)
            int ko = (c + 1) * BK + gc4;
            pfA0 = *(const float4*)(Asrc + (bm + grow0) * EMBED + ko);
            pfA1 = *(const float4*)(Asrc + (bm + grow1) * EMBED + ko);
            pfB0 = *(const float4*)(Bw   + (bn + grow0) * EMBED + ko);
            pfB1 = *(const float4*)(Bw   + (bn + grow1) * EMBED + ko);
        }

#pragma unroll
        for (int ks = 0; ks < 2; ks++) {
            uint32_t af[4][4], bf[4][2];
            const int kb = ks * 8;
#pragma unroll
            for (int i = 0; i < 4; i++) {
                int m = warp_m + i * 16;
                af[i][0] = *(const uint32_t*)&sA[(m + lr4    ) * SSTR + kb + lc4    ];
                af[i][1] = *(const uint32_t*)&sA[(m + lr4 + 8) * SSTR + kb + lc4    ];
                af[i][2] = *(const uint32_t*)&sA[(m + lr4    ) * SSTR + kb + lc4 + 4];
                af[i][3] = *(const uint32_t*)&sA[(m + lr4 + 8) * SSTR + kb + lc4 + 4];
            }
#pragma unroll
            for (int j = 0; j < 4; j++) {
                int n = warp_n + j * 8;
                bf[j][0] = *(const uint32_t*)&sB[(n + lr4) * SSTR + kb + lc4    ];
                bf[j][1] = *(const uint32_t*)&sB[(n + lr4) * SSTR + kb + lc4 + 4];
            }
#pragma unroll
            for (int i = 0; i < 4; i++)
#pragma unroll
                for (int j = 0; j < 4; j++)
                    mma_tf32(acc[i][j], af[i], bf[j]);
        }
    }

    // ---- epilogue: write fragments directly (float2 pairs) ----
#pragma unroll
    for (int i = 0; i < 4; i++) {
#pragma unroll
        for (int j = 0; j < 4; j++) {
            int row0 = bm + warp_m + i * 16 + lr4;
            int col0 = bn + warp_n + j * 8 + 2 * lc4;
#pragma unroll
            for (int half = 0; half < 2; half++) {
                int row = row0 + half * 8;
                float2 o;
                o.x = acc[i][j][half * 2 + 0];
                o.y = acc[i][j][half * 2 + 1];
                if (DST <= 2) {
                    o.x += __ldg(bias + col0 + 0);
                    o.y += __ldg(bias + col0 + 1);
                    int b   = row >> 11;
                    int tok = row & 2047;
                    int h   = col0 >> 6;
                    int dh  = col0 & 63;
                    float* C = (DST == 0) ? g_Q : (DST == 1) ? g_K : g_V;
                    *(float2*)&C[(((b << 4) + h) * SEQ + tok) * HDIM + dh] = o;
                } else {
                    *(float2*)&out[row * EMBED + col0] = o;
                }
            }
        }
    }
}

// ============================================================================
// Flash attention, fp32, reads g_Q/g_K/g_V, writes g_C. (unchanged, proven)
// ============================================================================
__global__ void __launch_bounds__(256)
attn_kernel()
{
    __shared__ float Qt[64 * 64];
    __shared__ float KP[64 * 64];
    __shared__ float Vs[64 * 64];

    const int tid = threadIdx.x;
    const int tq  = tid >> 4;
    const int tk  = tid & 15;
    const int qt  = blockIdx.x;
    const int h   = blockIdx.y;
    const int b   = blockIdx.z;
    const int q0  = qt * 64;

    const float* Qb = g_Q + ((b * HEADS + h) * SEQ + q0) * HDIM;
    const float* Kb = g_K + ((b * HEADS + h) * SEQ) * HDIM;
    const float* Vb = g_V + ((b * HEADS + h) * SEQ) * HDIM;

#pragma unroll
    for (int r = 0; r < 4; r++) {
        int idx = tid + r * 256;
        int row = idx >> 4;
        int c4  = (idx & 15) << 2;
        float4 qv = *(const float4*)&Qb[row * HDIM + c4];
        Qt[(c4 + 0) * 64 + row] = qv.x * 0.125f;
        Qt[(c4 + 1) * 64 + row] = qv.y * 0.125f;
        Qt[(c4 + 2) * 64 + row] = qv.z * 0.125f;
        Qt[(c4 + 3) * 64 + row] = qv.w * 0.125f;
    }

    float m[4], l[4], acc[4][4];
#pragma unroll
    for (int i = 0; i < 4; i++) {
        m[i] = -INFINITY;
        l[i] = 0.f;
#pragma unroll
        for (int j = 0; j < 4; j++) acc[i][j] = 0.f;
    }
    const int qi0 = tq * 4;
    const int dv0 = tk * 4;

    for (int kv0 = 0; kv0 < SEQ; kv0 += 64) {
        __syncthreads();
#pragma unroll
        for (int r = 0; r < 4; r++) {
            int idx = tid + r * 256;
            int row = idx >> 4;
            int c4  = (idx & 15) << 2;
            float4 kv = *(const float4*)&Kb[(kv0 + row) * HDIM + c4];
            KP[(c4 + 0) * 64 + row] = kv.x;
            KP[(c4 + 1) * 64 + row] = kv.y;
            KP[(c4 + 2) * 64 + row] = kv.z;
            KP[(c4 + 3) * 64 + row] = kv.w;
            *(float4*)&Vs[row * 64 + c4] =
                *(const float4*)&Vb[(kv0 + row) * HDIM + c4];
        }
        __syncthreads();

        float s[4][4];
#pragma unroll
        for (int i = 0; i < 4; i++)
#pragma unroll
            for (int j = 0; j < 4; j++) s[i][j] = 0.f;

#pragma unroll 8
        for (int d = 0; d < 64; d++) {
            float4 qv = *(const float4*)&Qt[d * 64 + qi0];
            float k0 = KP[d * 64 + tk];
            float k1 = KP[d * 64 + tk + 16];
            float k2 = KP[d * 64 + tk + 32];
            float k3 = KP[d * 64 + tk + 48];
            s[0][0] += qv.x * k0; s[0][1] += qv.x * k1; s[0][2] += qv.x * k2; s[0][3] += qv.x * k3;
            s[1][0] += qv.y * k0; s[1][1] += qv.y * k1; s[1][2] += qv.y * k2; s[1][3] += qv.y * k3;
            s[2][0] += qv.z * k0; s[2][1] += qv.z * k1; s[2][2] += qv.z * k2; s[2][3] += qv.z * k3;
            s[3][0] += qv.w * k0; s[3][1] += qv.w * k1; s[3][2] += qv.w * k2; s[3][3] += qv.w * k3;
        }
        __syncthreads();

#pragma unroll
        for (int i = 0; i < 4; i++) {
            float mx = fmaxf(fmaxf(s[i][0], s[i][1]), fmaxf(s[i][2], s[i][3]));
#pragma unroll
            for (int msk = 1; msk < 16; msk <<= 1)
                mx = fmaxf(mx, __shfl_xor_sync(0xffffffffu, mx, msk));
            float mnew = fmaxf(m[i], mx);
            float rs   = __expf(m[i] - mnew);
            m[i] = mnew;
            float p0 = __expf(s[i][0] - mnew);
            float p1 = __expf(s[i][1] - mnew);
            float p2 = __expf(s[i][2] - mnew);
            float p3 = __expf(s[i][3] - mnew);
            float ps = p0 + p1 + p2 + p3;
#pragma unroll
            for (int msk = 1; msk < 16; msk <<= 1)
                ps += __shfl_xor_sync(0xffffffffu, ps, msk);
            l[i] = l[i] * rs + ps;
#pragma unroll
            for (int j = 0; j < 4; j++) acc[i][j] *= rs;

            int kj;
            kj = tk;      KP[kj * 64 + ((tq ^ (kj & 7)) << 2) + i] = p0;
            kj = tk + 16; KP[kj * 64 + ((tq ^ (kj & 7)) << 2) + i] = p1;
            kj = tk + 32; KP[kj * 64 + ((tq ^ (kj & 7)) << 2) + i] = p2;
            kj = tk + 48; KP[kj * 64 + ((tq ^ (kj & 7)) << 2) + i] = p3;
        }
        __syncthreads();

#pragma unroll 8
        for (int kj = 0; kj < 64; kj++) {
            float4 vv = *(const float4*)&Vs[kj * 64 + dv0];
            float4 pv = *(const float4*)&KP[kj * 64 + ((tq ^ (kj & 7)) << 2)];
            acc[0][0] += pv.x * vv.x; acc[0][1] += pv.x * vv.y;
            acc[0][2] += pv.x * vv.z; acc[0][3] += pv.x * vv.w;
            acc[1][0] += pv.y * vv.x; acc[1][1] += pv.y * vv.y;
            acc[1][2] += pv.y * vv.z; acc[1][3] += pv.y * vv.w;
            acc[2][0] += pv.z * vv.x; acc[2][1] += pv.z * vv.y;
            acc[2][2] += pv.z * vv.z; acc[2][3] += pv.z * vv.w;
            acc[3][0] += pv.w * vv.x; acc[3][1] += pv.w * vv.y;
            acc[3][2] += pv.w * vv.z; acc[3][3] += pv.w * vv.w;
        }
    }

    float* Ob = g_C + (b * SEQ + q0) * EMBED + h * HDIM;
#pragma unroll
    for (int i = 0; i < 4; i++) {
        float inv = 1.f / l[i];
        float4 o;
        o.x = acc[i][0] * inv; o.y = acc[i][1] * inv;
        o.z = acc[i][2] * inv; o.w = acc[i][3] * inv;
        *(float4*)&Ob[(qi0 + i) * EMBED + dv0] = o;
    }
}

// ============================================================================
extern "C" void kernel_launch(void* const* d_in, const int* in_sizes, int n_in,
                              void* d_out, int out_size)
{
    (void)in_sizes; (void)n_in; (void)out_size;
    const float* x  = (const float*)d_in[0];
    const float* Wq = (const float*)d_in[1];
    const float* bq = (const float*)d_in[2];
    const float* Wk = (const float*)d_in[3];
    const float* bk = (const float*)d_in[4];
    const float* Wv = (const float*)d_in[5];
    const float* bv = (const float*)d_in[6];
    const float* Wo = (const float*)d_in[7];
    float* out = (float*)d_out;

    dim3 gg(MTOT / 128, EMBED / 128);   // 64 x 8
    mma_gemm<0><<<gg, 256>>>(x, Wq, bq, nullptr);
    mma_gemm<1><<<gg, 256>>>(x, Wk, bk, nullptr);
    mma_gemm<2><<<gg, 256>>>(x, Wv, bv, nullptr);

    attn_kernel<<<dim3(SEQ / 64, HEADS, BATCH), 256>>>();

    mma_gemm<3><<<gg, 256>>>(nullptr, Wo, nullptr, out);
}

// round 5
// speedup vs baseline: 3.7001x; 2.5535x over previous
#include <cuda_runtime.h>
#include <math.h>
#include <stdint.h>

#define EMBED 1024
#define HEADS 16
#define HDIM  64
#define BATCH 4
#define SEQ   2048
#define MTOT  (BATCH * SEQ)   /* 8192 */

#define BK      16            /* GEMM K elements per chunk */
#define NCHUNK  (EMBED / BK)  /* 64 */
#define SSTR    20            /* GEMM smem row stride */

// ---- scratch (device globals; no allocations allowed) ----
__device__ float g_Q[BATCH * HEADS * SEQ * HDIM];  // [B][H][N][Dh]
__device__ float g_K[BATCH * HEADS * SEQ * HDIM];
__device__ float g_V[BATCH * HEADS * SEQ * HDIM];
__device__ float g_C[MTOT * EMBED];                // attention ctx, [B][N][D]

// fp32 -> tf32 round-to-nearest (avoids biased truncation)
__device__ __forceinline__ float ftf32(float x) {
    uint32_t u;
    asm("cvt.rna.tf32.f32 %0, %1;" : "=r"(u) : "f"(x));
    return __uint_as_float(u);
}

// D += A(16x8) * B(8x8), tf32 inputs, fp32 accum
__device__ __forceinline__ void mma_tf32(float* d, const uint32_t* a, const uint32_t* b) {
    asm volatile(
        "mma.sync.aligned.m16n8k8.row.col.f32.tf32.tf32.f32 "
        "{%0,%1,%2,%3}, {%4,%5,%6,%7}, {%8,%9}, {%0,%1,%2,%3};"
        : "+f"(d[0]), "+f"(d[1]), "+f"(d[2]), "+f"(d[3])
        : "r"(a[0]), "r"(a[1]), "r"(a[2]), "r"(a[3]),
          "r"(b[0]), "r"(b[1]));
}

// ============================================================================
// mma.sync tf32 NT GEMM (unchanged from round 4, proven)
// ============================================================================
template <int DST>
__global__ void __launch_bounds__(256, 2)
mma_gemm(const float* __restrict__ Ain, const float* __restrict__ Bw,
         const float* __restrict__ bias, float* __restrict__ out)
{
    __shared__ float sA[128 * SSTR];
    __shared__ float sB[128 * SSTR];

    const float* Asrc = (DST == 3) ? (const float*)g_C : Ain;

    const int tid = threadIdx.x;
    const int wid = tid >> 5;
    const int lane = tid & 31;
    const int lr4 = lane >> 2;
    const int lc4 = lane & 3;
    const int warp_m = (wid & 1) * 64;
    const int warp_n = (wid >> 1) * 32;
    const int bm = blockIdx.x * 128;
    const int bn = blockIdx.y * 128;

    const int grow0 = tid >> 2;
    const int grow1 = (tid + 256) >> 2;
    const int gc4   = (tid & 3) << 2;

    float acc[4][4][4];
#pragma unroll
    for (int i = 0; i < 4; i++)
#pragma unroll
        for (int j = 0; j < 4; j++)
#pragma unroll
            for (int r = 0; r < 4; r++) acc[i][j][r] = 0.f;

    float4 pfA0, pfA1, pfB0, pfB1;
    pfA0 = *(const float4*)(Asrc + (bm + grow0) * EMBED + gc4);
    pfA1 = *(const float4*)(Asrc + (bm + grow1) * EMBED + gc4);
    pfB0 = *(const float4*)(Bw   + (bn + grow0) * EMBED + gc4);
    pfB1 = *(const float4*)(Bw   + (bn + grow1) * EMBED + gc4);

    for (int c = 0; c < NCHUNK; c++) {
        __syncthreads();
        float4 t;
        t.x = ftf32(pfA0.x); t.y = ftf32(pfA0.y); t.z = ftf32(pfA0.z); t.w = ftf32(pfA0.w);
        *(float4*)&sA[grow0 * SSTR + gc4] = t;
        t.x = ftf32(pfA1.x); t.y = ftf32(pfA1.y); t.z = ftf32(pfA1.z); t.w = ftf32(pfA1.w);
        *(float4*)&sA[grow1 * SSTR + gc4] = t;
        t.x = ftf32(pfB0.x); t.y = ftf32(pfB0.y); t.z = ftf32(pfB0.z); t.w = ftf32(pfB0.w);
        *(float4*)&sB[grow0 * SSTR + gc4] = t;
        t.x = ftf32(pfB1.x); t.y = ftf32(pfB1.y); t.z = ftf32(pfB1.z); t.w = ftf32(pfB1.w);
        *(float4*)&sB[grow1 * SSTR + gc4] = t;
        __syncthreads();

        if (c + 1 < NCHUNK) {
            int ko = (c + 1) * BK + gc4;
            pfA0 = *(const float4*)(Asrc + (bm + grow0) * EMBED + ko);
            pfA1 = *(const float4*)(Asrc + (bm + grow1) * EMBED + ko);
            pfB0 = *(const float4*)(Bw   + (bn + grow0) * EMBED + ko);
            pfB1 = *(const float4*)(Bw   + (bn + grow1) * EMBED + ko);
        }

#pragma unroll
        for (int ks = 0; ks < 2; ks++) {
            uint32_t af[4][4], bf[4][2];
            const int kb = ks * 8;
#pragma unroll
            for (int i = 0; i < 4; i++) {
                int m = warp_m + i * 16;
                af[i][0] = *(const uint32_t*)&sA[(m + lr4    ) * SSTR + kb + lc4    ];
                af[i][1] = *(const uint32_t*)&sA[(m + lr4 + 8) * SSTR + kb + lc4    ];
                af[i][2] = *(const uint32_t*)&sA[(m + lr4    ) * SSTR + kb + lc4 + 4];
                af[i][3] = *(const uint32_t*)&sA[(m + lr4 + 8) * SSTR + kb + lc4 + 4];
            }
#pragma unroll
            for (int j = 0; j < 4; j++) {
                int n = warp_n + j * 8;
                bf[j][0] = *(const uint32_t*)&sB[(n + lr4) * SSTR + kb + lc4    ];
                bf[j][1] = *(const uint32_t*)&sB[(n + lr4) * SSTR + kb + lc4 + 4];
            }
#pragma unroll
            for (int i = 0; i < 4; i++)
#pragma unroll
                for (int j = 0; j < 4; j++)
                    mma_tf32(acc[i][j], af[i], bf[j]);
        }
    }

#pragma unroll
    for (int i = 0; i < 4; i++) {
#pragma unroll
        for (int j = 0; j < 4; j++) {
            int row0 = bm + warp_m + i * 16 + lr4;
            int col0 = bn + warp_n + j * 8 + 2 * lc4;
#pragma unroll
            for (int half = 0; half < 2; half++) {
                int row = row0 + half * 8;
                float2 o;
                o.x = acc[i][j][half * 2 + 0];
                o.y = acc[i][j][half * 2 + 1];
                if (DST <= 2) {
                    o.x += __ldg(bias + col0 + 0);
                    o.y += __ldg(bias + col0 + 1);
                    int b   = row >> 11;
                    int tok = row & 2047;
                    int h   = col0 >> 6;
                    int dh  = col0 & 63;
                    float* C = (DST == 0) ? g_Q : (DST == 1) ? g_K : g_V;
                    *(float2*)&C[(((b << 4) + h) * SEQ + tok) * HDIM + dh] = o;
                } else {
                    *(float2*)&out[row * EMBED + col0] = o;
                }
            }
        }
    }
}

// ============================================================================
// Flash attention on mma.sync tf32.
// Block = 128 queries x one (b,h); 8 warps x 16 query rows; BKV=64.
// smem: swizzled sQ[128x64] (32KB) + sKV[64x64] (16KB, K then V^T per tile).
// P stays in registers: accumulator->A-frag via register reorder (c0,c2,c1,c3)
// + V^T stored with kv column permutation pi(l) = 2l / 2(l-4)+1.
// ============================================================================
__global__ void __launch_bounds__(256, 2)
attn_mma()
{
    __shared__ float sQ[128 * 64];
    __shared__ float sKV[64 * 64];

    const int tid  = threadIdx.x;
    const int wid  = tid >> 5;
    const int lane = tid & 31;
    const int lr4  = lane >> 2;
    const int lc4  = lane & 3;
    const int warp_m = wid * 16;
    const int q0 = blockIdx.x * 128;
    const int h  = blockIdx.y;
    const int b  = blockIdx.z;

    const float* Qb = g_Q + ((b * HEADS + h) * SEQ + q0) * HDIM;
    const float* Kb = g_K + ((b * HEADS + h) * SEQ) * HDIM;
    const float* Vb = g_V + ((b * HEADS + h) * SEQ) * HDIM;

    const uint32_t* sQu  = (const uint32_t*)sQ;
    const uint32_t* sKVu = (const uint32_t*)sKV;

    // Load Q (pre-scaled by Dh^-0.5 = 0.125, tf32-rounded), swizzled
#pragma unroll
    for (int r = 0; r < 8; r++) {
        int idx = tid + r * 256;
        int row = idx >> 4;
        int c4  = (idx & 15) << 2;
        float4 qv = *(const float4*)&Qb[row * HDIM + c4];
        float4 t;
        t.x = ftf32(qv.x * 0.125f); t.y = ftf32(qv.y * 0.125f);
        t.z = ftf32(qv.z * 0.125f); t.w = ftf32(qv.w * 0.125f);
        *(float4*)&sQ[row * 64 + (c4 ^ ((row & 7) << 2))] = t;
    }

    float out[8][4];
#pragma unroll
    for (int n = 0; n < 8; n++)
#pragma unroll
        for (int c = 0; c < 4; c++) out[n][c] = 0.f;
    float m0 = -INFINITY, m1 = -INFINITY, l0 = 0.f, l1 = 0.f;

    for (int kv0 = 0; kv0 < SEQ; kv0 += 64) {
        __syncthreads();   // prev PV reads of sKV done (and Q visible, iter 0)

        // K tile -> sKV (rows=kv, cols=dh), swizzled
#pragma unroll
        for (int r = 0; r < 4; r++) {
            int idx = tid + r * 256;
            int row = idx >> 4;
            int c4  = (idx & 15) << 2;
            float4 kv = *(const float4*)&Kb[(kv0 + row) * HDIM + c4];
            float4 t;
            t.x = ftf32(kv.x); t.y = ftf32(kv.y); t.z = ftf32(kv.z); t.w = ftf32(kv.w);
            *(float4*)&sKV[row * 64 + (c4 ^ ((row & 7) << 2))] = t;
        }
        __syncthreads();

        // QK^T: scores s[j] = 16q x 8kv tiles, j = 0..7
        float s[8][4];
#pragma unroll
        for (int j = 0; j < 8; j++)
#pragma unroll
            for (int c = 0; c < 4; c++) s[j][c] = 0.f;

#pragma unroll
        for (int k = 0; k < 8; k++) {
            const int kb = k * 8;
            uint32_t a[4];
            const int ra = warp_m + lr4;
            a[0] = sQu[ra * 64       + ((kb + lc4    ) ^ (lr4 << 2))];
            a[1] = sQu[(ra + 8) * 64 + ((kb + lc4    ) ^ (lr4 << 2))];
            a[2] = sQu[ra * 64       + ((kb + lc4 + 4) ^ (lr4 << 2))];
            a[3] = sQu[(ra + 8) * 64 + ((kb + lc4 + 4) ^ (lr4 << 2))];
#pragma unroll
            for (int j = 0; j < 8; j++) {
                uint32_t bf[2];
                const int rb = j * 8 + lr4;
                bf[0] = sKVu[rb * 64 + ((kb + lc4    ) ^ (lr4 << 2))];
                bf[1] = sKVu[rb * 64 + ((kb + lc4 + 4) ^ (lr4 << 2))];
                mma_tf32(s[j], a, bf);
            }
        }
        __syncthreads();   // K reads done; sKV reusable

        // V tile -> sKV transposed (rows=dh, cols=kv) with kv permutation:
        // logical col l holds V row base + pi(l); invpi(r) = (r>>1) + ((r&1)<<2)
#pragma unroll
        for (int r = 0; r < 4; r++) {
            int kvr = (tid >> 2) & 63;
            int c4  = ((tid & 3) << 2) + (r << 4);
            float4 vv = *(const float4*)&Vb[(kv0 + kvr) * HDIM + c4];
            int colv = (kvr & 56) + ((kvr >> 1) & 3) + ((kvr & 1) << 2);
            sKV[(c4 + 0) * 64 + (colv ^ (((c4 + 0) & 7) << 2))] = ftf32(vv.x);
            sKV[(c4 + 1) * 64 + (colv ^ (((c4 + 1) & 7) << 2))] = ftf32(vv.y);
            sKV[(c4 + 2) * 64 + (colv ^ (((c4 + 2) & 7) << 2))] = ftf32(vv.z);
            sKV[(c4 + 3) * 64 + (colv ^ (((c4 + 3) & 7) << 2))] = ftf32(vv.w);
        }

        // Online softmax (registers only; overlaps V store latency)
        float mx0 = -INFINITY, mx1 = -INFINITY;
#pragma unroll
        for (int j = 0; j < 8; j++) {
            mx0 = fmaxf(mx0, fmaxf(s[j][0], s[j][1]));
            mx1 = fmaxf(mx1, fmaxf(s[j][2], s[j][3]));
        }
        mx0 = fmaxf(mx0, __shfl_xor_sync(0xffffffffu, mx0, 1));
        mx0 = fmaxf(mx0, __shfl_xor_sync(0xffffffffu, mx0, 2));
        mx1 = fmaxf(mx1, __shfl_xor_sync(0xffffffffu, mx1, 1));
        mx1 = fmaxf(mx1, __shfl_xor_sync(0xffffffffu, mx1, 2));
        float mn0 = fmaxf(m0, mx0), mn1 = fmaxf(m1, mx1);
        float rs0 = __expf(m0 - mn0), rs1 = __expf(m1 - mn1);
        m0 = mn0; m1 = mn1;
        float sum0 = 0.f, sum1 = 0.f;
#pragma unroll
        for (int j = 0; j < 8; j++) {
            s[j][0] = __expf(s[j][0] - mn0);
            s[j][1] = __expf(s[j][1] - mn0);
            sum0 += s[j][0] + s[j][1];
            s[j][2] = __expf(s[j][2] - mn1);
            s[j][3] = __expf(s[j][3] - mn1);
            sum1 += s[j][2] + s[j][3];
        }
        sum0 += __shfl_xor_sync(0xffffffffu, sum0, 1);
        sum0 += __shfl_xor_sync(0xffffffffu, sum0, 2);
        sum1 += __shfl_xor_sync(0xffffffffu, sum1, 1);
        sum1 += __shfl_xor_sync(0xffffffffu, sum1, 2);
        l0 = l0 * rs0 + sum0;
        l1 = l1 * rs1 + sum1;
#pragma unroll
        for (int n = 0; n < 8; n++) {
            out[n][0] *= rs0; out[n][1] *= rs0;
            out[n][2] *= rs1; out[n][3] *= rs1;
        }
#pragma unroll
        for (int j = 0; j < 8; j++)
#pragma unroll
            for (int c = 0; c < 4; c++) s[j][c] = ftf32(s[j][c]);
        __syncthreads();   // V^T ready

        // PV: out[n] += P_tile(j) @ Vt ; A-frag = (c0, c2, c1, c3) of s[j]
#pragma unroll
        for (int j = 0; j < 8; j++) {
            uint32_t a[4];
            a[0] = __float_as_uint(s[j][0]);
            a[1] = __float_as_uint(s[j][2]);
            a[2] = __float_as_uint(s[j][1]);
            a[3] = __float_as_uint(s[j][3]);
            const int kb = j * 8;
#pragma unroll
            for (int n = 0; n < 8; n++) {
                uint32_t bf[2];
                const int rb = n * 8 + lr4;
                bf[0] = sKVu[rb * 64 + ((kb + lc4    ) ^ (lr4 << 2))];
                bf[1] = sKVu[rb * 64 + ((kb + lc4 + 4) ^ (lr4 << 2))];
                mma_tf32(out[n], a, bf);
            }
        }
    }

    // Epilogue: ctx[b][q][h*64 + dh]
    const float inv0 = 1.f / l0, inv1 = 1.f / l1;
    float* Cb = g_C + (b * SEQ + q0) * EMBED + h * HDIM;
    const int r0 = warp_m + lr4, r1 = r0 + 8;
#pragma unroll
    for (int n = 0; n < 8; n++) {
        int col = n * 8 + 2 * lc4;
        float2 o;
        o.x = out[n][0] * inv0; o.y = out[n][1] * inv0;
        *(float2*)&Cb[r0 * EMBED + col] = o;
        o.x = out[n][2] * inv1; o.y = out[n][3] * inv1;
        *(float2*)&Cb[r1 * EMBED + col] = o;
    }
}

// ============================================================================
extern "C" void kernel_launch(void* const* d_in, const int* in_sizes, int n_in,
                              void* d_out, int out_size)
{
    (void)in_sizes; (void)n_in; (void)out_size;
    const float* x  = (const float*)d_in[0];
    const float* Wq = (const float*)d_in[1];
    const float* bq = (const float*)d_in[2];
    const float* Wk = (const float*)d_in[3];
    const float* bk = (const float*)d_in[4];
    const float* Wv = (const float*)d_in[5];
    const float* bv = (const float*)d_in[6];
    const float* Wo = (const float*)d_in[7];
    float* out = (float*)d_out;

    dim3 gg(MTOT / 128, EMBED / 128);   // 64 x 8
    mma_gemm<0><<<gg, 256>>>(x, Wq, bq, nullptr);
    mma_gemm<1><<<gg, 256>>>(x, Wk, bk, nullptr);
    mma_gemm<2><<<gg, 256>>>(x, Wv, bv, nullptr);

    attn_mma<<<dim3(SEQ / 128, HEADS, BATCH), 256>>>();

    mma_gemm<3><<<gg, 256>>>(nullptr, Wo, nullptr, out);
}

// round 6
// speedup vs baseline: 3.7131x; 1.0035x over previous
#include <cuda_runtime.h>
#include <math.h>
#include <stdint.h>

#define EMBED 1024
#define HEADS 16
#define HDIM  64
#define BATCH 4
#define SEQ   2048
#define MTOT  (BATCH * SEQ)   /* 8192 */

#define BK      16            /* GEMM K elements per chunk */
#define NCHUNK  (EMBED / BK)  /* 64 */
#define SSTR    20            /* GEMM smem row stride */

// ---- scratch (device globals; no allocations allowed) ----
__device__ float g_Q[BATCH * HEADS * SEQ * HDIM];  // [B][H][N][Dh]
__device__ float g_K[BATCH * HEADS * SEQ * HDIM];
__device__ float g_V[BATCH * HEADS * SEQ * HDIM];
__device__ float g_C[MTOT * EMBED];                // attention ctx, [B][N][D]

// fp32 -> tf32 round-to-nearest (avoids biased truncation)
__device__ __forceinline__ float ftf32(float x) {
    uint32_t u;
    asm("cvt.rna.tf32.f32 %0, %1;" : "=r"(u) : "f"(x));
    return __uint_as_float(u);
}

// D += A(16x8) * B(8x8), tf32 inputs, fp32 accum
__device__ __forceinline__ void mma_tf32(float* d, const uint32_t* a, const uint32_t* b) {
    asm volatile(
        "mma.sync.aligned.m16n8k8.row.col.f32.tf32.tf32.f32 "
        "{%0,%1,%2,%3}, {%4,%5,%6,%7}, {%8,%9}, {%0,%1,%2,%3};"
        : "+f"(d[0]), "+f"(d[1]), "+f"(d[2]), "+f"(d[3])
        : "r"(a[0]), "r"(a[1]), "r"(a[2]), "r"(a[3]),
          "r"(b[0]), "r"(b[1]));
}

// ============================================================================
// Double-buffered tf32 NT GEMM mainloop (shared by both GEMM kernels).
// BM=BN=128, BK=16, 256 threads (8 warps, 2m x 4n), warp tile 64x32.
// One __syncthreads per chunk; next chunk's smem store issued before this
// chunk's mma (cross-buffer, race-free).
// ============================================================================
__device__ __forceinline__ void gemm_main(const float* __restrict__ Asrc,
                                          const float* __restrict__ Bw,
                                          int bm, int bn,
                                          float (&acc)[4][4][4])
{
    __shared__ float sA[2][128 * SSTR];
    __shared__ float sB[2][128 * SSTR];

    const int tid  = threadIdx.x;
    const int wid  = tid >> 5;
    const int lane = tid & 31;
    const int lr4  = lane >> 2;
    const int lc4  = lane & 3;
    const int warp_m = (wid & 1) * 64;
    const int warp_n = (wid >> 1) * 32;

    const int grow0 = tid >> 2;          // 0..63
    const int grow1 = grow0 + 64;        // 64..127
    const int gc4   = (tid & 3) << 2;

    float4 pA0, pA1, pB0, pB1;

#define LOADPF(cc) do { int ko = (cc) * BK + gc4; \
    pA0 = *(const float4*)(Asrc + (bm + grow0) * EMBED + ko); \
    pA1 = *(const float4*)(Asrc + (bm + grow1) * EMBED + ko); \
    pB0 = *(const float4*)(Bw   + (bn + grow0) * EMBED + ko); \
    pB1 = *(const float4*)(Bw   + (bn + grow1) * EMBED + ko); } while (0)

#define STOREPF(buf) do { float4 t; \
    t.x = ftf32(pA0.x); t.y = ftf32(pA0.y); t.z = ftf32(pA0.z); t.w = ftf32(pA0.w); \
    *(float4*)&sA[buf][grow0 * SSTR + gc4] = t; \
    t.x = ftf32(pA1.x); t.y = ftf32(pA1.y); t.z = ftf32(pA1.z); t.w = ftf32(pA1.w); \
    *(float4*)&sA[buf][grow1 * SSTR + gc4] = t; \
    t.x = ftf32(pB0.x); t.y = ftf32(pB0.y); t.z = ftf32(pB0.z); t.w = ftf32(pB0.w); \
    *(float4*)&sB[buf][grow0 * SSTR + gc4] = t; \
    t.x = ftf32(pB1.x); t.y = ftf32(pB1.y); t.z = ftf32(pB1.z); t.w = ftf32(pB1.w); \
    *(float4*)&sB[buf][grow1 * SSTR + gc4] = t; } while (0)

    LOADPF(0);
    STOREPF(0);
    LOADPF(1);

    for (int c = 0; c < NCHUNK; c++) {
        __syncthreads();                 // buf[c&1] stores visible to all
        if (c + 1 < NCHUNK) {
            STOREPF((c + 1) & 1);        // safe: readers of that buf passed barrier
            if (c + 2 < NCHUNK) LOADPF(c + 2);
        }
        const float* cA = sA[c & 1];
        const float* cB = sB[c & 1];

#pragma unroll
        for (int ks = 0; ks < 2; ks++) {
            uint32_t af[4][4], bf[4][2];
            const int kb = ks * 8;
#pragma unroll
            for (int i = 0; i < 4; i++) {
                int m = warp_m + i * 16;
                af[i][0] = *(const uint32_t*)&cA[(m + lr4    ) * SSTR + kb + lc4    ];
                af[i][1] = *(const uint32_t*)&cA[(m + lr4 + 8) * SSTR + kb + lc4    ];
                af[i][2] = *(const uint32_t*)&cA[(m + lr4    ) * SSTR + kb + lc4 + 4];
                af[i][3] = *(const uint32_t*)&cA[(m + lr4 + 8) * SSTR + kb + lc4 + 4];
            }
#pragma unroll
            for (int j = 0; j < 4; j++) {
                int n = warp_n + j * 8;
                bf[j][0] = *(const uint32_t*)&cB[(n + lr4) * SSTR + kb + lc4    ];
                bf[j][1] = *(const uint32_t*)&cB[(n + lr4) * SSTR + kb + lc4 + 4];
            }
#pragma unroll
            for (int i = 0; i < 4; i++)
#pragma unroll
                for (int j = 0; j < 4; j++)
                    mma_tf32(acc[i][j], af[i], bf[j]);
        }
    }
#undef LOADPF
#undef STOREPF
}

// ============================================================================
// Fused QKV projection: blockIdx.z selects (W, bias, dst in {g_Q,g_K,g_V}).
// ============================================================================
__global__ void __launch_bounds__(256, 2)
qkv_gemm(const float* __restrict__ x,
         const float* __restrict__ Wq, const float* __restrict__ Wk,
         const float* __restrict__ Wv,
         const float* __restrict__ bq, const float* __restrict__ bk,
         const float* __restrict__ bv)
{
    const int z = blockIdx.z;
    const float* Bw   = (z == 0) ? Wq : (z == 1) ? Wk : Wv;
    const float* bias = (z == 0) ? bq : (z == 1) ? bk : bv;
    float* C          = (z == 0) ? g_Q : (z == 1) ? g_K : g_V;

    const int bm = blockIdx.x * 128;
    const int bn = blockIdx.y * 128;

    float acc[4][4][4];
#pragma unroll
    for (int i = 0; i < 4; i++)
#pragma unroll
        for (int j = 0; j < 4; j++)
#pragma unroll
            for (int r = 0; r < 4; r++) acc[i][j][r] = 0.f;

    gemm_main(x, Bw, bm, bn, acc);

    const int tid  = threadIdx.x;
    const int wid  = tid >> 5;
    const int lane = tid & 31;
    const int lr4  = lane >> 2;
    const int lc4  = lane & 3;
    const int warp_m = (wid & 1) * 64;
    const int warp_n = (wid >> 1) * 32;

#pragma unroll
    for (int i = 0; i < 4; i++) {
#pragma unroll
        for (int j = 0; j < 4; j++) {
            int row0 = bm + warp_m + i * 16 + lr4;
            int col0 = bn + warp_n + j * 8 + 2 * lc4;
#pragma unroll
            for (int half = 0; half < 2; half++) {
                int row = row0 + half * 8;
                float2 o;
                o.x = acc[i][j][half * 2 + 0] + __ldg(bias + col0 + 0);
                o.y = acc[i][j][half * 2 + 1] + __ldg(bias + col0 + 1);
                int b   = row >> 11;
                int tok = row & 2047;
                int h   = col0 >> 6;
                int dh  = col0 & 63;
                *(float2*)&C[(((b << 4) + h) * SEQ + tok) * HDIM + dh] = o;
            }
        }
    }
}

// ============================================================================
// Output projection: A = g_C (by name), C -> out row-major, no bias.
// ============================================================================
__global__ void __launch_bounds__(256, 2)
out_gemm(const float* __restrict__ Wo, float* __restrict__ out)
{
    const int bm = blockIdx.x * 128;
    const int bn = blockIdx.y * 128;

    float acc[4][4][4];
#pragma unroll
    for (int i = 0; i < 4; i++)
#pragma unroll
        for (int j = 0; j < 4; j++)
#pragma unroll
            for (int r = 0; r < 4; r++) acc[i][j][r] = 0.f;

    gemm_main((const float*)g_C, Wo, bm, bn, acc);

    const int tid  = threadIdx.x;
    const int wid  = tid >> 5;
    const int lane = tid & 31;
    const int lr4  = lane >> 2;
    const int lc4  = lane & 3;
    const int warp_m = (wid & 1) * 64;
    const int warp_n = (wid >> 1) * 32;

#pragma unroll
    for (int i = 0; i < 4; i++) {
#pragma unroll
        for (int j = 0; j < 4; j++) {
            int row0 = bm + warp_m + i * 16 + lr4;
            int col0 = bn + warp_n + j * 8 + 2 * lc4;
#pragma unroll
            for (int half = 0; half < 2; half++) {
                int row = row0 + half * 8;
                float2 o;
                o.x = acc[i][j][half * 2 + 0];
                o.y = acc[i][j][half * 2 + 1];
                *(float2*)&out[row * EMBED + col0] = o;
            }
        }
    }
}

// ============================================================================
// Flash attention on mma.sync tf32 (unchanged from round 5, proven).
// ============================================================================
__global__ void __launch_bounds__(256, 2)
attn_mma()
{
    __shared__ float sQ[128 * 64];
    __shared__ float sKV[64 * 64];

    const int tid  = threadIdx.x;
    const int wid  = tid >> 5;
    const int lane = tid & 31;
    const int lr4  = lane >> 2;
    const int lc4  = lane & 3;
    const int warp_m = wid * 16;
    const int q0 = blockIdx.x * 128;
    const int h  = blockIdx.y;
    const int b  = blockIdx.z;

    const float* Qb = g_Q + ((b * HEADS + h) * SEQ + q0) * HDIM;
    const float* Kb = g_K + ((b * HEADS + h) * SEQ) * HDIM;
    const float* Vb = g_V + ((b * HEADS + h) * SEQ) * HDIM;

    const uint32_t* sQu  = (const uint32_t*)sQ;
    const uint32_t* sKVu = (const uint32_t*)sKV;

#pragma unroll
    for (int r = 0; r < 8; r++) {
        int idx = tid + r * 256;
        int row = idx >> 4;
        int c4  = (idx & 15) << 2;
        float4 qv = *(const float4*)&Qb[row * HDIM + c4];
        float4 t;
        t.x = ftf32(qv.x * 0.125f); t.y = ftf32(qv.y * 0.125f);
        t.z = ftf32(qv.z * 0.125f); t.w = ftf32(qv.w * 0.125f);
        *(float4*)&sQ[row * 64 + (c4 ^ ((row & 7) << 2))] = t;
    }

    float out[8][4];
#pragma unroll
    for (int n = 0; n < 8; n++)
#pragma unroll
        for (int c = 0; c < 4; c++) out[n][c] = 0.f;
    float m0 = -INFINITY, m1 = -INFINITY, l0 = 0.f, l1 = 0.f;

    for (int kv0 = 0; kv0 < SEQ; kv0 += 64) {
        __syncthreads();

#pragma unroll
        for (int r = 0; r < 4; r++) {
            int idx = tid + r * 256;
            int row = idx >> 4;
            int c4  = (idx & 15) << 2;
            float4 kv = *(const float4*)&Kb[(kv0 + row) * HDIM + c4];
            float4 t;
            t.x = ftf32(kv.x); t.y = ftf32(kv.y); t.z = ftf32(kv.z); t.w = ftf32(kv.w);
            *(float4*)&sKV[row * 64 + (c4 ^ ((row & 7) << 2))] = t;
        }
        __syncthreads();

        float s[8][4];
#pragma unroll
        for (int j = 0; j < 8; j++)
#pragma unroll
            for (int c = 0; c < 4; c++) s[j][c] = 0.f;

#pragma unroll
        for (int k = 0; k < 8; k++) {
            const int kb = k * 8;
            uint32_t a[4];
            const int ra = warp_m + lr4;
            a[0] = sQu[ra * 64       + ((kb + lc4    ) ^ (lr4 << 2))];
            a[1] = sQu[(ra + 8) * 64 + ((kb + lc4    ) ^ (lr4 << 2))];
            a[2] = sQu[ra * 64       + ((kb + lc4 + 4) ^ (lr4 << 2))];
            a[3] = sQu[(ra + 8) * 64 + ((kb + lc4 + 4) ^ (lr4 << 2))];
#pragma unroll
            for (int j = 0; j < 8; j++) {
                uint32_t bf[2];
                const int rb = j * 8 + lr4;
                bf[0] = sKVu[rb * 64 + ((kb + lc4    ) ^ (lr4 << 2))];
                bf[1] = sKVu[rb * 64 + ((kb + lc4 + 4) ^ (lr4 << 2))];
                mma_tf32(s[j], a, bf);
            }
        }
        __syncthreads();

#pragma unroll
        for (int r = 0; r < 4; r++) {
            int kvr = (tid >> 2) & 63;
            int c4  = ((tid & 3) << 2) + (r << 4);
            float4 vv = *(const float4*)&Vb[(kv0 + kvr) * HDIM + c4];
            int colv = (kvr & 56) + ((kvr >> 1) & 3) + ((kvr & 1) << 2);
            sKV[(c4 + 0) * 64 + (colv ^ (((c4 + 0) & 7) << 2))] = ftf32(vv.x);
            sKV[(c4 + 1) * 64 + (colv ^ (((c4 + 1) & 7) << 2))] = ftf32(vv.y);
            sKV[(c4 + 2) * 64 + (colv ^ (((c4 + 2) & 7) << 2))] = ftf32(vv.z);
            sKV[(c4 + 3) * 64 + (colv ^ (((c4 + 3) & 7) << 2))] = ftf32(vv.w);
        }

        float mx0 = -INFINITY, mx1 = -INFINITY;
#pragma unroll
        for (int j = 0; j < 8; j++) {
            mx0 = fmaxf(mx0, fmaxf(s[j][0], s[j][1]));
            mx1 = fmaxf(mx1, fmaxf(s[j][2], s[j][3]));
        }
        mx0 = fmaxf(mx0, __shfl_xor_sync(0xffffffffu, mx0, 1));
        mx0 = fmaxf(mx0, __shfl_xor_sync(0xffffffffu, mx0, 2));
        mx1 = fmaxf(mx1, __shfl_xor_sync(0xffffffffu, mx1, 1));
        mx1 = fmaxf(mx1, __shfl_xor_sync(0xffffffffu, mx1, 2));
        float mn0 = fmaxf(m0, mx0), mn1 = fmaxf(m1, mx1);
        float rs0 = __expf(m0 - mn0), rs1 = __expf(m1 - mn1);
        m0 = mn0; m1 = mn1;
        float sum0 = 0.f, sum1 = 0.f;
#pragma unroll
        for (int j = 0; j < 8; j++) {
            s[j][0] = __expf(s[j][0] - mn0);
            s[j][1] = __expf(s[j][1] - mn0);
            sum0 += s[j][0] + s[j][1];
            s[j][2] = __expf(s[j][2] - mn1);
            s[j][3] = __expf(s[j][3] - mn1);
            sum1 += s[j][2] + s[j][3];
        }
        sum0 += __shfl_xor_sync(0xffffffffu, sum0, 1);
        sum0 += __shfl_xor_sync(0xffffffffu, sum0, 2);
        sum1 += __shfl_xor_sync(0xffffffffu, sum1, 1);
        sum1 += __shfl_xor_sync(0xffffffffu, sum1, 2);
        l0 = l0 * rs0 + sum0;
        l1 = l1 * rs1 + sum1;
#pragma unroll
        for (int n = 0; n < 8; n++) {
            out[n][0] *= rs0; out[n][1] *= rs0;
            out[n][2] *= rs1; out[n][3] *= rs1;
        }
#pragma unroll
        for (int j = 0; j < 8; j++)
#pragma unroll
            for (int c = 0; c < 4; c++) s[j][c] = ftf32(s[j][c]);
        __syncthreads();

#pragma unroll
        for (int j = 0; j < 8; j++) {
            uint32_t a[4];
            a[0] = __float_as_uint(s[j][0]);
            a[1] = __float_as_uint(s[j][2]);
            a[2] = __float_as_uint(s[j][1]);
            a[3] = __float_as_uint(s[j][3]);
            const int kb = j * 8;
#pragma unroll
            for (int n = 0; n < 8; n++) {
                uint32_t bf[2];
                const int rb = n * 8 + lr4;
                bf[0] = sKVu[rb * 64 + ((kb + lc4    ) ^ (lr4 << 2))];
                bf[1] = sKVu[rb * 64 + ((kb + lc4 + 4) ^ (lr4 << 2))];
                mma_tf32(out[n], a, bf);
            }
        }
    }

    const float inv0 = 1.f / l0, inv1 = 1.f / l1;
    float* Cb = g_C + (b * SEQ + q0) * EMBED + h * HDIM;
    const int r0 = warp_m + lr4, r1 = r0 + 8;
#pragma unroll
    for (int n = 0; n < 8; n++) {
        int col = n * 8 + 2 * lc4;
        float2 o;
        o.x = out[n][0] * inv0; o.y = out[n][1] * inv0;
        *(float2*)&Cb[r0 * EMBED + col] = o;
        o.x = out[n][2] * inv1; o.y = out[n][3] * inv1;
        *(float2*)&Cb[r1 * EMBED + col] = o;
    }
}

// ============================================================================
extern "C" void kernel_launch(void* const* d_in, const int* in_sizes, int n_in,
                              void* d_out, int out_size)
{
    (void)in_sizes; (void)n_in; (void)out_size;
    const float* x  = (const float*)d_in[0];
    const float* Wq = (const float*)d_in[1];
    const float* bq = (const float*)d_in[2];
    const float* Wk = (const float*)d_in[3];
    const float* bk = (const float*)d_in[4];
    const float* Wv = (const float*)d_in[5];
    const float* bv = (const float*)d_in[6];
    const float* Wo = (const float*)d_in[7];
    float* out = (float*)d_out;

    qkv_gemm<<<dim3(MTOT / 128, EMBED / 128, 3), 256>>>(x, Wq, Wk, Wv, bq, bk, bv);

    attn_mma<<<dim3(SEQ / 128, HEADS, BATCH), 256>>>();

    out_gemm<<<dim3(MTOT / 128, EMBED / 128), 256>>>(Wo, out);
}